// round 14
// baseline (speedup 1.0000x reference)
#include <cuda_runtime.h>

#define NN 512
#define PP 130816
typedef unsigned long long ull;

__device__ float g_ca[NN*512];
__device__ float g_cb[NN*512];
__device__ float g_sa[NN*256];
__device__ float g_sb[NN*256];
__device__ float g_ca2[NN*512];
__device__ float g_cb2[NN*512];
__device__ float g_sa2[NN*256];
__device__ float g_sb2[NN*256];

__constant__ __align__(16) float c_w2[5120];   // cw2 [512][10] row-major
__constant__ __align__(16) float c_sw2[256];

__device__ __forceinline__ ull pack2(float lo, float hi) {
    ull r; asm("mov.b64 %0, {%1, %2};" : "=l"(r) : "f"(lo), "f"(hi)); return r;
}
__device__ __forceinline__ void fma2(ull& d, ull a, ull b) {
    asm("fma.rn.f32x2 %0, %1, %2, %0;" : "+l"(d) : "l"(a), "l"(b));
}
__device__ __forceinline__ ull add2(ull a, ull b) {
    ull r; asm("add.rn.f32x2 %0, %1, %2;" : "=l"(r) : "l"(a), "l"(b)); return r;
}
__device__ __forceinline__ float2 unpack2(ull v) {
    float2 f; asm("mov.b64 {%0, %1}, %2;" : "=f"(f.x), "=f"(f.y) : "l"(v)); return f;
}

// ---------------------------------------------------------------------------
// Phase 1: K-split proj GEMM (R12, measured 35.6us). grid (24,8,2).
// ---------------------------------------------------------------------------
__global__ __launch_bounds__(256) void proj_gemm(const float* __restrict__ F,
                                                 const float* __restrict__ cw1,
                                                 const float* __restrict__ sw1) {
    __shared__ __align__(16) float As[32 * 68];
    __shared__ __align__(16) ull  Bs[32 * 64];
    int t = threadIdx.x;
    int ks = blockIdx.z;
    int cglob = blockIdx.x * 64;
    const float* Bp; float* Cp; int ldb, bcol;
    if (cglob < 512)       { Bp = cw1;             Cp = ks ? g_ca2 : g_ca; ldb = 512; bcol = cglob; }
    else if (cglob < 1024) { Bp = cw1 + 512 * 512; Cp = ks ? g_cb2 : g_cb; ldb = 512; bcol = cglob - 512; }
    else if (cglob < 1280) { Bp = sw1;             Cp = ks ? g_sa2 : g_sa; ldb = 256; bcol = cglob - 1024; }
    else                   { Bp = sw1 + 512 * 256; Cp = ks ? g_sb2 : g_sb; ldb = 256; bcol = cglob - 1280; }
    int rb = blockIdx.y * 64;
    int kbase = ks * 256;
    int rowg = t & 15, colg = t >> 4;

    ull acc[2][4];
#pragma unroll
    for (int a = 0; a < 2; a++)
#pragma unroll
        for (int b = 0; b < 4; b++) acc[a][b] = 0ull;

    for (int tile = 0; tile < 8; tile++) {
        int k0 = kbase + tile * 32;
#pragma unroll
        for (int it = 0; it < 2; it++) {
            int idx = t + it * 256, row = idx >> 3, q8 = idx & 7;
            float4 v = *(const float4*)&F[(rb + row) * 512 + k0 + q8 * 4];
            As[(q8 * 4 + 0) * 68 + row] = v.x;
            As[(q8 * 4 + 1) * 68 + row] = v.y;
            As[(q8 * 4 + 2) * 68 + row] = v.z;
            As[(q8 * 4 + 3) * 68 + row] = v.w;
        }
#pragma unroll
        for (int it = 0; it < 2; it++) {
            int idx = t + it * 256, k = idx >> 4, q16 = idx & 15;
            float4 v = *(const float4*)&Bp[(k0 + k) * ldb + bcol + q16 * 4];
            Bs[k * 64 + q16 * 4 + 0] = pack2(v.x, v.x);
            Bs[k * 64 + q16 * 4 + 1] = pack2(v.y, v.y);
            Bs[k * 64 + q16 * 4 + 2] = pack2(v.z, v.z);
            Bs[k * 64 + q16 * 4 + 3] = pack2(v.w, v.w);
        }
        __syncthreads();
#pragma unroll
        for (int k = 0; k < 32; k++) {
            ulonglong2 aA = *(const ulonglong2*)&As[k * 68 + rowg * 4];
            ulonglong2 b0 = *(const ulonglong2*)&Bs[k * 64 + colg * 4];
            ulonglong2 b1 = *(const ulonglong2*)&Bs[k * 64 + colg * 4 + 2];
            fma2(acc[0][0], aA.x, b0.x); fma2(acc[0][1], aA.x, b0.y);
            fma2(acc[0][2], aA.x, b1.x); fma2(acc[0][3], aA.x, b1.y);
            fma2(acc[1][0], aA.y, b0.x); fma2(acc[1][1], aA.y, b0.y);
            fma2(acc[1][2], aA.y, b1.x); fma2(acc[1][3], aA.y, b1.y);
        }
        __syncthreads();
    }
#pragma unroll
    for (int mp = 0; mp < 2; mp++) {
        int r = rb + rowg * 4 + mp * 2;
#pragma unroll
        for (int n = 0; n < 4; n++) {
            float2 f = unpack2(acc[mp][n]);
            int c = bcol + colg * 4 + n;
            Cp[r * ldb + c] = f.x;
            Cp[(r + 1) * ldb + c] = f.y;
        }
    }
}

// ---------------------------------------------------------------------------
// Phase 2 (R10 structure + CONSTANT weights): 1024 thr = 32 warps, 32j x 32i.
// wg = w&15 -> i = 2wg, 2wg+1 (2 pairs/lane); half = w>>4 -> k-half.
// Weights via LDC on the constant port (no smem/LSU). Class-paired acc.
// smem floats: bC 32x516 (cb1+proj-halves folded) | aC [16wg][512k][2i].
// Strength overlays; k-half reduction via smem.
// ---------------------------------------------------------------------------
#define O_BC 0
#define O_AC 16512
#define SMEMF 32896

__global__ __launch_bounds__(1024) void pair_kernel(
    const float* __restrict__ cb1, const float* __restrict__ cb2,
    const float* __restrict__ sb1, const float* __restrict__ sb2,
    float* __restrict__ out)
{
    extern __shared__ float sm[];
    int bid = blockIdx.x;
    int jb = (int)((sqrtf(8.0f * bid + 1.0f) - 1.0f) * 0.5f);
    while ((jb + 1) * (jb + 2) / 2 <= bid) jb++;
    while (jb * (jb + 1) / 2 > bid) jb--;
    int ib = bid - jb * (jb + 1) / 2;
    int jbase = jb * 32, ibase = ib * 32;
    int t = threadIdx.x;
    int w = t >> 5, lane = t & 31;
    int wg = w & 15, half = w >> 4;

    // bC = g_cb + g_cb2 + cb1
#pragma unroll
    for (int it = 0; it < 4; it++) {
        int idx = t + it * 1024;
        int r = idx >> 7, q = (idx & 127) * 4;
        float4 v1 = *(const float4*)&g_cb[(jbase + r) * 512 + q];
        float4 v2 = *(const float4*)&g_cb2[(jbase + r) * 512 + q];
        float4 vc = *(const float4*)&cb1[q];
        v1.x += v2.x + vc.x; v1.y += v2.y + vc.y;
        v1.z += v2.z + vc.z; v1.w += v2.w + vc.w;
        *(float4*)&sm[O_BC + r * 516 + q] = v1;
    }
    // aC interleaved [wg][k][2] = g_ca + g_ca2
#pragma unroll
    for (int it = 0; it < 4; it++) {
        int idx = t + it * 1024;
        int r = idx >> 7, q = (idx & 127) * 4;
        float4 v1 = *(const float4*)&g_ca[(ibase + r) * 512 + q];
        float4 v2 = *(const float4*)&g_ca2[(ibase + r) * 512 + q];
        float* dst = &sm[O_AC + (r >> 1) * 1024 + q * 2 + (r & 1)];
        dst[0] = v1.x + v2.x; dst[2] = v1.y + v2.y;
        dst[4] = v1.z + v2.z; dst[6] = v1.w + v2.w;
    }
    __syncthreads();

    const float* bRow = &sm[O_BC + lane * 516];
    const float* aP   = &sm[O_AC + wg * 1024];
    const ull*   wC   = (const ull*)c_w2;       // ull index = 5*k + q

    ull acc0[5], acc1[5];
#pragma unroll
    for (int q = 0; q < 5; q++) { acc0[q] = 0ull; acc1[q] = 0ull; }

    int koff = half * 256;
    for (int k0 = koff; k0 < koff + 256; k0 += 4) {
        float4 bv = *(const float4*)(bRow + k0);
        ulonglong2 aA = *(const ulonglong2*)(aP + 2 * k0);
        ulonglong2 aB = *(const ulonglong2*)(aP + 2 * k0 + 4);
        ull ap[4] = {aA.x, aA.y, aB.x, aB.y};
        float bf[4] = {bv.x, bv.y, bv.z, bv.w};
#pragma unroll
        for (int kk = 0; kk < 4; kk++) {
            ull s = add2(ap[kk], pack2(bf[kk], bf[kk]));
            float2 f = unpack2(s);
            float h0 = fmaxf(f.x, 0.f), h1 = fmaxf(f.y, 0.f);
            ull hh0 = pack2(h0, h0), hh1 = pack2(h1, h1);
            const ull* wr = wC + (k0 + kk) * 5;
#pragma unroll
            for (int q = 0; q < 5; q++) {
                ull wq = wr[q];
                fma2(acc0[q], hh0, wq);
                fma2(acc1[q], hh1, wq);
            }
        }
    }

    // strength overlay
    __syncthreads();
#pragma unroll
    for (int it = 0; it < 2; it++) {
        int idx = t + it * 1024;
        int r = idx >> 6, q = (idx & 63) * 4;
        float4 v1 = *(const float4*)&g_sb[(jbase + r) * 256 + q];
        float4 v2 = *(const float4*)&g_sb2[(jbase + r) * 256 + q];
        float4 vc = *(const float4*)&sb1[q];
        v1.x += v2.x + vc.x; v1.y += v2.y + vc.y;
        v1.z += v2.z + vc.z; v1.w += v2.w + vc.w;
        *(float4*)&sm[O_BC + r * 260 + q] = v1;
    }
#pragma unroll
    for (int it = 0; it < 2; it++) {
        int idx = t + it * 1024;
        int r = idx >> 6, q = (idx & 63) * 4;
        float4 v1 = *(const float4*)&g_sa[(ibase + r) * 256 + q];
        float4 v2 = *(const float4*)&g_sa2[(ibase + r) * 256 + q];
        float* dst = &sm[O_AC + (r >> 1) * 512 + q * 2 + (r & 1)];
        dst[0] = v1.x + v2.x; dst[2] = v1.y + v2.y;
        dst[4] = v1.z + v2.z; dst[6] = v1.w + v2.w;
    }
    __syncthreads();

    float s0 = 0.f, s1 = 0.f;
    {
        const float* sbRow = &sm[O_BC + lane * 260];
        const float* saP   = &sm[O_AC + wg * 512];
        int k2 = half * 128;
        for (int k0 = k2; k0 < k2 + 128; k0 += 4) {
            float4 bv = *(const float4*)(sbRow + k0);
            ulonglong2 aA = *(const ulonglong2*)(saP + 2 * k0);
            ulonglong2 aB = *(const ulonglong2*)(saP + 2 * k0 + 4);
            float4 wv = *(const float4*)&c_sw2[k0];
            ull ap[4] = {aA.x, aA.y, aB.x, aB.y};
            float bf[4] = {bv.x, bv.y, bv.z, bv.w};
            float wf[4] = {wv.x, wv.y, wv.z, wv.w};
#pragma unroll
            for (int kk = 0; kk < 4; kk++) {
                ull s = add2(ap[kk], pack2(bf[kk], bf[kk]));
                float2 f = unpack2(s);
                s0 = fmaf(fmaxf(f.x, 0.f), wf[kk], s0);
                s1 = fmaf(fmaxf(f.y, 0.f), wf[kk], s1);
            }
        }
    }

    // k-half reduction
    __syncthreads();
    ull* red = (ull*)&sm[O_AC];
    int rbase = (wg * 11) * 32 + lane;
    if (half == 1) {
#pragma unroll
        for (int q = 0; q < 5; q++) {
            red[rbase + q * 32] = acc0[q];
            red[rbase + (5 + q) * 32] = acc1[q];
        }
        red[rbase + 10 * 32] = pack2(s0, s1);
    }
    __syncthreads();

    if (half == 0) {
#pragma unroll
        for (int q = 0; q < 5; q++) {
            acc0[q] = add2(acc0[q], red[rbase + q * 32]);
            acc1[q] = add2(acc1[q], red[rbase + (5 + q) * 32]);
        }
        float2 rs = unpack2(red[rbase + 10 * 32]);
        s0 += rs.x; s1 += rs.y;

        int j = jbase + lane;
        float b2[10];
#pragma unroll
        for (int c = 0; c < 10; c++) b2[c] = __ldg(&cb2[c]);
        float sbv = __ldg(&sb2[0]);
        float sv[2] = {s0, s1};
#pragma unroll
        for (int s = 0; s < 2; s++) {
            int i = ibase + 2 * wg + s;
            if (j <= i) continue;
            float l[10];
#pragma unroll
            for (int q = 0; q < 5; q++) {
                float2 f = unpack2(s ? acc1[q] : acc0[q]);
                l[2 * q] = f.x + b2[2 * q];
                l[2 * q + 1] = f.y + b2[2 * q + 1];
            }
            float m = l[0]; int idx = 0;
#pragma unroll
            for (int c = 1; c < 10; c++) if (l[c] > m) { m = l[c]; idx = c; }
            float sum = 0.f;
#pragma unroll
            for (int c = 0; c < 10; c++) sum += __expf(l[c] - m);
            float lse = m + __logf(sum);
            int p = i * (1023 - i) / 2 + j - i - 1;
            float2* o2 = (float2*)(out + (size_t)p * 10);
#pragma unroll
            for (int q = 0; q < 5; q++)
                o2[q] = make_float2(l[2 * q] - lse, l[2 * q + 1] - lse);
            out[10 * PP + p] = (float)idx;
            float x = sv[s] + sbv;
            out[11 * PP + p] = 1.f / (1.f + __expf(-x));
        }
    }
}

extern "C" void kernel_launch(void* const* d_in, const int* in_sizes, int n_in,
                              void* d_out, int out_size) {
    (void)in_sizes; (void)n_in; (void)out_size;
    const float* features = (const float*)d_in[0];
    const float* cw1 = (const float*)d_in[1];
    const float* cb1 = (const float*)d_in[2];
    const float* cw2 = (const float*)d_in[3];
    const float* cb2 = (const float*)d_in[4];
    const float* sw1 = (const float*)d_in[5];
    const float* sb1 = (const float*)d_in[6];
    const float* sw2 = (const float*)d_in[7];
    const float* sb2 = (const float*)d_in[8];
    float* out = (float*)d_out;

    cudaMemcpyToSymbolAsync(c_w2, cw2, 5120 * sizeof(float), 0,
                            cudaMemcpyDeviceToDevice, 0);
    cudaMemcpyToSymbolAsync(c_sw2, sw2, 256 * sizeof(float), 0,
                            cudaMemcpyDeviceToDevice, 0);
    cudaFuncSetAttribute(pair_kernel, cudaFuncAttributeMaxDynamicSharedMemorySize,
                         SMEMF * sizeof(float));

    proj_gemm<<<dim3(24, 8, 2), 256>>>(features, cw1, sw1);
    pair_kernel<<<136, 1024, SMEMF * sizeof(float)>>>(
        cb1, cb2, sb1, sb2, out);
}

// round 16
// speedup vs baseline: 1.0572x; 1.0572x over previous
#include <cuda_runtime.h>

#define NN 512
#define PP 130816
typedef unsigned long long ull;

__device__ float g_ca[NN*512];
__device__ float g_cb[NN*512];
__device__ float g_sa[NN*256];
__device__ float g_sb[NN*256];
__device__ float g_ca2[NN*512];
__device__ float g_cb2[NN*512];
__device__ float g_sa2[NN*256];
__device__ float g_sb2[NN*256];

__device__ __forceinline__ ull pack2(float lo, float hi) {
    ull r; asm("mov.b64 %0, {%1, %2};" : "=l"(r) : "f"(lo), "f"(hi)); return r;
}
__device__ __forceinline__ void fma2(ull& d, ull a, ull b) {
    asm("fma.rn.f32x2 %0, %1, %2, %0;" : "+l"(d) : "l"(a), "l"(b));
}
__device__ __forceinline__ ull add2(ull a, ull b) {
    ull r; asm("add.rn.f32x2 %0, %1, %2;" : "=l"(r) : "l"(a), "l"(b)); return r;
}
__device__ __forceinline__ float2 unpack2(ull v) {
    float2 f; asm("mov.b64 {%0, %1}, %2;" : "=f"(f.x), "=f"(f.y) : "l"(v)); return f;
}
__device__ __forceinline__ ull relu2(ull s) {
    float2 f = unpack2(s);
    return pack2(fmaxf(f.x, 0.f), fmaxf(f.y, 0.f));
}

// ---------------------------------------------------------------------------
// Phase 1: K-split proj GEMM, DOUBLE-BUFFERED. grid (24,8,2), 256 thr.
// dsm: As float[2][2176] | Bs ull[2][2048]  (50176 B)
// ---------------------------------------------------------------------------
__global__ __launch_bounds__(256) void proj_gemm(const float* __restrict__ F,
                                                 const float* __restrict__ cw1,
                                                 const float* __restrict__ sw1) {
    extern __shared__ float dsm[];
    float* As = dsm;
    ull*   Bs = (ull*)(dsm + 4352);
    int t = threadIdx.x;
    int ks = blockIdx.z;
    int cglob = blockIdx.x * 64;
    const float* Bp; float* Cp; int ldb, bcol;
    if (cglob < 512)       { Bp = cw1;             Cp = ks ? g_ca2 : g_ca; ldb = 512; bcol = cglob; }
    else if (cglob < 1024) { Bp = cw1 + 512 * 512; Cp = ks ? g_cb2 : g_cb; ldb = 512; bcol = cglob - 512; }
    else if (cglob < 1280) { Bp = sw1;             Cp = ks ? g_sa2 : g_sa; ldb = 256; bcol = cglob - 1024; }
    else                   { Bp = sw1 + 512 * 256; Cp = ks ? g_sb2 : g_sb; ldb = 256; bcol = cglob - 1280; }
    int rb = blockIdx.y * 64;
    int kbase = ks * 256;
    int rowg = t & 15, colg = t >> 4;
    int rowA = t >> 3, q8A = t & 7;
    int kB = t >> 4, q16 = t & 15;

    ull acc[2][4];
#pragma unroll
    for (int a = 0; a < 2; a++)
#pragma unroll
        for (int b = 0; b < 4; b++) acc[a][b] = 0ull;

    float4 pa0, pa1, pb0, pb1;
    pa0 = *(const float4*)&F[(rb + rowA) * 512 + kbase + q8A * 4];
    pa1 = *(const float4*)&F[(rb + rowA + 32) * 512 + kbase + q8A * 4];
    pb0 = *(const float4*)&Bp[(kbase + kB) * ldb + bcol + q16 * 4];
    pb1 = *(const float4*)&Bp[(kbase + kB + 16) * ldb + bcol + q16 * 4];
#pragma unroll
    for (int it = 0; it < 2; it++) {
        float4 v = it ? pa1 : pa0;
        int row = rowA + it * 32;
        As[(q8A * 4 + 0) * 68 + row] = v.x;
        As[(q8A * 4 + 1) * 68 + row] = v.y;
        As[(q8A * 4 + 2) * 68 + row] = v.z;
        As[(q8A * 4 + 3) * 68 + row] = v.w;
    }
#pragma unroll
    for (int it = 0; it < 2; it++) {
        float4 v = it ? pb1 : pb0;
        int k = kB + it * 16;
        Bs[k * 64 + q16 * 4 + 0] = pack2(v.x, v.x);
        Bs[k * 64 + q16 * 4 + 1] = pack2(v.y, v.y);
        Bs[k * 64 + q16 * 4 + 2] = pack2(v.z, v.z);
        Bs[k * 64 + q16 * 4 + 3] = pack2(v.w, v.w);
    }
    __syncthreads();

    for (int tile = 0; tile < 8; tile++) {
        int cur = tile & 1;
        if (tile < 7) {
            int k0 = kbase + (tile + 1) * 32;
            pa0 = *(const float4*)&F[(rb + rowA) * 512 + k0 + q8A * 4];
            pa1 = *(const float4*)&F[(rb + rowA + 32) * 512 + k0 + q8A * 4];
            pb0 = *(const float4*)&Bp[(k0 + kB) * ldb + bcol + q16 * 4];
            pb1 = *(const float4*)&Bp[(k0 + kB + 16) * ldb + bcol + q16 * 4];
        }
        const float* Ac = As + cur * 2176;
        const ull*   Bc = Bs + cur * 2048;
#pragma unroll
        for (int k = 0; k < 32; k++) {
            ulonglong2 aA = *(const ulonglong2*)&Ac[k * 68 + rowg * 4];
            ulonglong2 b0 = *(const ulonglong2*)&Bc[k * 64 + colg * 4];
            ulonglong2 b1 = *(const ulonglong2*)&Bc[k * 64 + colg * 4 + 2];
            fma2(acc[0][0], aA.x, b0.x); fma2(acc[0][1], aA.x, b0.y);
            fma2(acc[0][2], aA.x, b1.x); fma2(acc[0][3], aA.x, b1.y);
            fma2(acc[1][0], aA.y, b0.x); fma2(acc[1][1], aA.y, b0.y);
            fma2(acc[1][2], aA.y, b1.x); fma2(acc[1][3], aA.y, b1.y);
        }
        if (tile < 7) {
            int nxt = cur ^ 1;
            float* An = As + nxt * 2176;
            ull*   Bn = Bs + nxt * 2048;
#pragma unroll
            for (int it = 0; it < 2; it++) {
                float4 v = it ? pa1 : pa0;
                int row = rowA + it * 32;
                An[(q8A * 4 + 0) * 68 + row] = v.x;
                An[(q8A * 4 + 1) * 68 + row] = v.y;
                An[(q8A * 4 + 2) * 68 + row] = v.z;
                An[(q8A * 4 + 3) * 68 + row] = v.w;
            }
#pragma unroll
            for (int it = 0; it < 2; it++) {
                float4 v = it ? pb1 : pb0;
                int k = kB + it * 16;
                Bn[k * 64 + q16 * 4 + 0] = pack2(v.x, v.x);
                Bn[k * 64 + q16 * 4 + 1] = pack2(v.y, v.y);
                Bn[k * 64 + q16 * 4 + 2] = pack2(v.z, v.z);
                Bn[k * 64 + q16 * 4 + 3] = pack2(v.w, v.w);
            }
        }
        __syncthreads();
    }
#pragma unroll
    for (int mp = 0; mp < 2; mp++) {
        int r = rb + rowg * 4 + mp * 2;
#pragma unroll
        for (int n = 0; n < 4; n++) {
            float2 f = unpack2(acc[mp][n]);
            int c = bcol + colg * 4 + n;
            Cp[r * ldb + c] = f.x;
            Cp[(r + 1) * ldb + c] = f.y;
        }
    }
}

// ---------------------------------------------------------------------------
// Phase 2: 1024 thr = 32 warps, 32j x 32i, occ 50%. wg = w&15 -> i = 2wg,2wg+1
// (2 pairs/lane); half = w>>4 -> k in [256h,+256). K-PAIRED h + kp-paired w2.
// smem: bC 32x516 (all folds) | aC 32x512 plain | wp 2560 ull | swp 128 ull.
// ---------------------------------------------------------------------------
#define O_BC 0
#define O_AC 16512
#define O_WP 32896
#define O_SW 38016
#define SMEMF 38272

__global__ __launch_bounds__(1024) void pair_kernel(
    const float* __restrict__ cb1, const float* __restrict__ cw2,
    const float* __restrict__ cb2, const float* __restrict__ sb1,
    const float* __restrict__ sw2, const float* __restrict__ sb2,
    float* __restrict__ out)
{
    extern __shared__ float sm[];
    int bid = blockIdx.x;
    int jb = (int)((sqrtf(8.0f * bid + 1.0f) - 1.0f) * 0.5f);
    while ((jb + 1) * (jb + 2) / 2 <= bid) jb++;
    while (jb * (jb + 1) / 2 > bid) jb--;
    int ib = bid - jb * (jb + 1) / 2;
    int jbase = jb * 32, ibase = ib * 32;
    int t = threadIdx.x;
    int w = t >> 5, lane = t & 31;
    int wg = w & 15, half = w >> 4;

#pragma unroll
    for (int it = 0; it < 4; it++) {
        int idx = t + it * 1024;
        int r = idx >> 7, q = (idx & 127) * 4;
        float4 v1 = *(const float4*)&g_cb[(jbase + r) * 512 + q];
        float4 v2 = *(const float4*)&g_cb2[(jbase + r) * 512 + q];
        float4 vc = *(const float4*)&cb1[q];
        v1.x += v2.x + vc.x; v1.y += v2.y + vc.y;
        v1.z += v2.z + vc.z; v1.w += v2.w + vc.w;
        *(float4*)&sm[O_BC + r * 516 + q] = v1;
    }
#pragma unroll
    for (int it = 0; it < 4; it++) {
        int idx = t + it * 1024;
        int r = idx >> 7, q = (idx & 127) * 4;
        float4 v1 = *(const float4*)&g_ca[(ibase + r) * 512 + q];
        float4 v2 = *(const float4*)&g_ca2[(ibase + r) * 512 + q];
        v1.x += v2.x; v1.y += v2.y; v1.z += v2.z; v1.w += v2.w;
        *(float4*)&sm[O_AC + r * 512 + q] = v1;
    }
    {
        ull* wp = (ull*)&sm[O_WP];
        for (int idx = t; idx < 2560; idx += 1024) {
            int kp = idx / 10, c = idx - kp * 10;
            wp[idx] = pack2(cw2[kp * 20 + c], cw2[kp * 20 + 10 + c]);
        }
    }
    if (t < 128) ((ull*)&sm[O_SW])[t] = pack2(sw2[2 * t], sw2[2 * t + 1]);
    __syncthreads();

    const float* bRow  = &sm[O_BC + lane * 516];
    const float* aRow0 = &sm[O_AC + (2 * wg) * 512];
    const float* aRow1 = aRow0 + 512;
    const ull*   wp    = (const ull*)&sm[O_WP];

    ull acc0[10], acc1[10];
#pragma unroll
    for (int c = 0; c < 10; c++) { acc0[c] = 0ull; acc1[c] = 0ull; }

    int koff = half * 256;
    for (int k0 = koff; k0 < koff + 256; k0 += 4) {
        ulonglong2 bp = *(const ulonglong2*)(bRow + k0);
        ulonglong2 a0 = *(const ulonglong2*)(aRow0 + k0);
        ulonglong2 a1 = *(const ulonglong2*)(aRow1 + k0);
        ull h0x = relu2(add2(a0.x, bp.x)), h0y = relu2(add2(a0.y, bp.y));
        ull h1x = relu2(add2(a1.x, bp.x)), h1y = relu2(add2(a1.y, bp.y));
        const ulonglong2* wA = (const ulonglong2*)(wp + (k0 >> 1) * 10);
        const ulonglong2* wB = (const ulonglong2*)(wp + (k0 >> 1) * 10 + 10);
#pragma unroll
        for (int q = 0; q < 5; q++) {
            ulonglong2 wa = wA[q];
            fma2(acc0[2 * q], h0x, wa.x); fma2(acc0[2 * q + 1], h0x, wa.y);
            fma2(acc1[2 * q], h1x, wa.x); fma2(acc1[2 * q + 1], h1x, wa.y);
            ulonglong2 wb = wB[q];
            fma2(acc0[2 * q], h0y, wb.x); fma2(acc0[2 * q + 1], h0y, wb.y);
            fma2(acc1[2 * q], h1y, wb.x); fma2(acc1[2 * q + 1], h1y, wb.y);
        }
    }

    __syncthreads();
#pragma unroll
    for (int it = 0; it < 2; it++) {
        int idx = t + it * 1024;
        int r = idx >> 6, q = (idx & 63) * 4;
        float4 v1 = *(const float4*)&g_sb[(jbase + r) * 256 + q];
        float4 v2 = *(const float4*)&g_sb2[(jbase + r) * 256 + q];
        float4 vc = *(const float4*)&sb1[q];
        v1.x += v2.x + vc.x; v1.y += v2.y + vc.y;
        v1.z += v2.z + vc.z; v1.w += v2.w + vc.w;
        *(float4*)&sm[O_BC + r * 260 + q] = v1;
    }
#pragma unroll
    for (int it = 0; it < 2; it++) {
        int idx = t + it * 1024;
        int r = idx >> 6, q = (idx & 63) * 4;
        float4 v1 = *(const float4*)&g_sa[(ibase + r) * 256 + q];
        float4 v2 = *(const float4*)&g_sa2[(ibase + r) * 256 + q];
        v1.x += v2.x; v1.y += v2.y; v1.z += v2.z; v1.w += v2.w;
        *(float4*)&sm[O_AC + r * 256 + q] = v1;
    }
    __syncthreads();

    ull sacc0 = 0ull, sacc1 = 0ull;
    {
        const float* sbRow = &sm[O_BC + lane * 260];
        const float* sRow0 = &sm[O_AC + (2 * wg) * 256];
        const float* sRow1 = sRow0 + 256;
        const ull* swp = (const ull*)&sm[O_SW];
        int k2 = half * 128;
        for (int k0 = k2; k0 < k2 + 128; k0 += 4) {
            ulonglong2 bp = *(const ulonglong2*)(sbRow + k0);
            ulonglong2 a0 = *(const ulonglong2*)(sRow0 + k0);
            ulonglong2 a1 = *(const ulonglong2*)(sRow1 + k0);
            ulonglong2 ww = *(const ulonglong2*)(swp + (k0 >> 1));
            fma2(sacc0, relu2(add2(a0.x, bp.x)), ww.x);
            fma2(sacc0, relu2(add2(a0.y, bp.y)), ww.y);
            fma2(sacc1, relu2(add2(a1.x, bp.x)), ww.x);
            fma2(sacc1, relu2(add2(a1.y, bp.y)), ww.y);
        }
    }

    float part[22];
#pragma unroll
    for (int c = 0; c < 10; c++) {
        float2 f0 = unpack2(acc0[c]); part[c] = f0.x + f0.y;
        float2 f1 = unpack2(acc1[c]); part[10 + c] = f1.x + f1.y;
    }
    { float2 s = unpack2(sacc0); part[20] = s.x + s.y; }
    { float2 s = unpack2(sacc1); part[21] = s.x + s.y; }

    __syncthreads();
    float* red = sm;
    int rbase = wg * 22 * 32 + lane;
    if (half == 1) {
#pragma unroll
        for (int s = 0; s < 22; s++) red[rbase + s * 32] = part[s];
    }
    __syncthreads();

    if (half == 0) {
#pragma unroll
        for (int s = 0; s < 22; s++) part[s] += red[rbase + s * 32];

        int j = jbase + lane;
        float b2[10];
#pragma unroll
        for (int c = 0; c < 10; c++) b2[c] = __ldg(&cb2[c]);
        float sbv = __ldg(&sb2[0]);
#pragma unroll
        for (int s = 0; s < 2; s++) {
            int i = ibase + 2 * wg + s;
            if (j <= i) continue;
            float l[10];
#pragma unroll
            for (int c = 0; c < 10; c++) l[c] = part[10 * s + c] + b2[c];
            float m = l[0]; int idx = 0;
#pragma unroll
            for (int c = 1; c < 10; c++) if (l[c] > m) { m = l[c]; idx = c; }
            float sum = 0.f;
#pragma unroll
            for (int c = 0; c < 10; c++) sum += __expf(l[c] - m);
            float lse = m + __logf(sum);
            int p = i * (1023 - i) / 2 + j - i - 1;
            float2* o2 = (float2*)(out + (size_t)p * 10);
#pragma unroll
            for (int q = 0; q < 5; q++)
                o2[q] = make_float2(l[2 * q] - lse, l[2 * q + 1] - lse);
            out[10 * PP + p] = (float)idx;
            float x = part[20 + s] + sbv;
            out[11 * PP + p] = 1.f / (1.f + __expf(-x));
        }
    }
}

extern "C" void kernel_launch(void* const* d_in, const int* in_sizes, int n_in,
                              void* d_out, int out_size) {
    (void)in_sizes; (void)n_in; (void)out_size;
    const float* features = (const float*)d_in[0];
    const float* cw1 = (const float*)d_in[1];
    const float* cb1 = (const float*)d_in[2];
    const float* cw2 = (const float*)d_in[3];
    const float* cb2 = (const float*)d_in[4];
    const float* sw1 = (const float*)d_in[5];
    const float* sb1 = (const float*)d_in[6];
    const float* sw2 = (const float*)d_in[7];
    const float* sb2 = (const float*)d_in[8];
    float* out = (float*)d_out;

    cudaFuncSetAttribute(proj_gemm, cudaFuncAttributeMaxDynamicSharedMemorySize, 50176);
    cudaFuncSetAttribute(pair_kernel, cudaFuncAttributeMaxDynamicSharedMemorySize,
                         SMEMF * sizeof(float));

    proj_gemm<<<dim3(24, 8, 2), 256, 50176>>>(features, cw1, sw1);
    pair_kernel<<<136, 1024, SMEMF * sizeof(float)>>>(
        cb1, cw2, cb2, sb1, sw2, sb2, out);
}

// round 17
// speedup vs baseline: 1.0589x; 1.0016x over previous
#include <cuda_runtime.h>

#define NN 512
#define PP 130816
#define NSPLIT 4
typedef unsigned long long ull;

__device__ float g_ca[NSPLIT*NN*512];
__device__ float g_cb[NSPLIT*NN*512];
__device__ float g_sa[NSPLIT*NN*256];
__device__ float g_sb[NSPLIT*NN*256];

__device__ __forceinline__ ull pack2(float lo, float hi) {
    ull r; asm("mov.b64 %0, {%1, %2};" : "=l"(r) : "f"(lo), "f"(hi)); return r;
}
__device__ __forceinline__ void fma2(ull& d, ull a, ull b) {
    asm("fma.rn.f32x2 %0, %1, %2, %0;" : "+l"(d) : "l"(a), "l"(b));
}
__device__ __forceinline__ ull add2(ull a, ull b) {
    ull r; asm("add.rn.f32x2 %0, %1, %2;" : "=l"(r) : "l"(a), "l"(b)); return r;
}
__device__ __forceinline__ float2 unpack2(ull v) {
    float2 f; asm("mov.b64 {%0, %1}, %2;" : "=f"(f.x), "=f"(f.y) : "l"(v)); return f;
}

// ---------------------------------------------------------------------------
// Phase 1: K-split x4 proj GEMM (R12 structure). grid (24,8,4), 256 thr.
// Each block: BM=64, BN=64, K=128 (4 tiles of BK=32). Segment ks writes
// g_*[ks*NN*cols ...]; pair staging sums the 4 segments.
// ---------------------------------------------------------------------------
__global__ __launch_bounds__(256) void proj_gemm(const float* __restrict__ F,
                                                 const float* __restrict__ cw1,
                                                 const float* __restrict__ sw1) {
    __shared__ __align__(16) float As[32 * 68];
    __shared__ __align__(16) ull  Bs[32 * 64];
    int t = threadIdx.x;
    int ks = blockIdx.z;
    int cglob = blockIdx.x * 64;
    const float* Bp; float* Cp; int ldb, bcol;
    if (cglob < 512)       { Bp = cw1;             Cp = g_ca + ks * NN * 512; ldb = 512; bcol = cglob; }
    else if (cglob < 1024) { Bp = cw1 + 512 * 512; Cp = g_cb + ks * NN * 512; ldb = 512; bcol = cglob - 512; }
    else if (cglob < 1280) { Bp = sw1;             Cp = g_sa + ks * NN * 256; ldb = 256; bcol = cglob - 1024; }
    else                   { Bp = sw1 + 512 * 256; Cp = g_sb + ks * NN * 256; ldb = 256; bcol = cglob - 1280; }
    int rb = blockIdx.y * 64;
    int kbase = ks * 128;
    int rowg = t & 15, colg = t >> 4;

    ull acc[2][4];
#pragma unroll
    for (int a = 0; a < 2; a++)
#pragma unroll
        for (int b = 0; b < 4; b++) acc[a][b] = 0ull;

    for (int tile = 0; tile < 4; tile++) {
        int k0 = kbase + tile * 32;
#pragma unroll
        for (int it = 0; it < 2; it++) {
            int idx = t + it * 256, row = idx >> 3, q8 = idx & 7;
            float4 v = *(const float4*)&F[(rb + row) * 512 + k0 + q8 * 4];
            As[(q8 * 4 + 0) * 68 + row] = v.x;
            As[(q8 * 4 + 1) * 68 + row] = v.y;
            As[(q8 * 4 + 2) * 68 + row] = v.z;
            As[(q8 * 4 + 3) * 68 + row] = v.w;
        }
#pragma unroll
        for (int it = 0; it < 2; it++) {
            int idx = t + it * 256, k = idx >> 4, q16 = idx & 15;
            float4 v = *(const float4*)&Bp[(k0 + k) * ldb + bcol + q16 * 4];
            Bs[k * 64 + q16 * 4 + 0] = pack2(v.x, v.x);
            Bs[k * 64 + q16 * 4 + 1] = pack2(v.y, v.y);
            Bs[k * 64 + q16 * 4 + 2] = pack2(v.z, v.z);
            Bs[k * 64 + q16 * 4 + 3] = pack2(v.w, v.w);
        }
        __syncthreads();
#pragma unroll
        for (int k = 0; k < 32; k++) {
            ulonglong2 aA = *(const ulonglong2*)&As[k * 68 + rowg * 4];
            ulonglong2 b0 = *(const ulonglong2*)&Bs[k * 64 + colg * 4];
            ulonglong2 b1 = *(const ulonglong2*)&Bs[k * 64 + colg * 4 + 2];
            fma2(acc[0][0], aA.x, b0.x); fma2(acc[0][1], aA.x, b0.y);
            fma2(acc[0][2], aA.x, b1.x); fma2(acc[0][3], aA.x, b1.y);
            fma2(acc[1][0], aA.y, b0.x); fma2(acc[1][1], aA.y, b0.y);
            fma2(acc[1][2], aA.y, b1.x); fma2(acc[1][3], aA.y, b1.y);
        }
        __syncthreads();
    }
#pragma unroll
    for (int mp = 0; mp < 2; mp++) {
        int r = rb + rowg * 4 + mp * 2;
#pragma unroll
        for (int n = 0; n < 4; n++) {
            float2 f = unpack2(acc[mp][n]);
            int c = bcol + colg * 4 + n;
            Cp[r * ldb + c] = f.x;
            Cp[(r + 1) * ldb + c] = f.y;
        }
    }
}

// ---------------------------------------------------------------------------
// Phase 2: R10 pair kernel verbatim (measured 52.2us), staging sums 4 segments.
// 1024 thr = 32 warps, 32j x 32i; wg = w&15 -> i = 2wg,2wg+1; half = w>>4.
// smem floats: bC 32x516 (cb1 folded) | aC [16wg][512k][2i] | w2 512x12 pad.
// ---------------------------------------------------------------------------
#define O_BC 0
#define O_AC 16512
#define O_WC 32896
#define SMEMF 39040

__global__ __launch_bounds__(1024) void pair_kernel(
    const float* __restrict__ cb1, const float* __restrict__ cw2,
    const float* __restrict__ cb2, const float* __restrict__ sb1,
    const float* __restrict__ sw2, const float* __restrict__ sb2,
    float* __restrict__ out)
{
    extern __shared__ float sm[];
    int bid = blockIdx.x;
    int jb = (int)((sqrtf(8.0f * bid + 1.0f) - 1.0f) * 0.5f);
    while ((jb + 1) * (jb + 2) / 2 <= bid) jb++;
    while (jb * (jb + 1) / 2 > bid) jb--;
    int ib = bid - jb * (jb + 1) / 2;
    int jbase = jb * 32, ibase = ib * 32;
    int t = threadIdx.x;
    int w = t >> 5, lane = t & 31;
    int wg = w & 15, half = w >> 4;

    // bC = sum of 4 segments + cb1
#pragma unroll
    for (int it = 0; it < 4; it++) {
        int idx = t + it * 1024;
        int r = idx >> 7, q = (idx & 127) * 4;
        int off = (jbase + r) * 512 + q;
        float4 v = *(const float4*)&cb1[q];
#pragma unroll
        for (int s = 0; s < NSPLIT; s++) {
            float4 u = *(const float4*)&g_cb[s * NN * 512 + off];
            v.x += u.x; v.y += u.y; v.z += u.z; v.w += u.w;
        }
        *(float4*)&sm[O_BC + r * 516 + q] = v;
    }
    // aC interleaved [wg][k][2] = sum of 4 segments
#pragma unroll
    for (int it = 0; it < 4; it++) {
        int idx = t + it * 1024;
        int r = idx >> 7, q = (idx & 127) * 4;
        int off = (ibase + r) * 512 + q;
        float4 v = {0.f, 0.f, 0.f, 0.f};
#pragma unroll
        for (int s = 0; s < NSPLIT; s++) {
            float4 u = *(const float4*)&g_ca[s * NN * 512 + off];
            v.x += u.x; v.y += u.y; v.z += u.z; v.w += u.w;
        }
        float* dst = &sm[O_AC + (r >> 1) * 1024 + q * 2 + (r & 1)];
        dst[0] = v.x; dst[2] = v.y; dst[4] = v.z; dst[6] = v.w;
    }
    // w2 rows padded to 12
    for (int idx = t; idx < 5120; idx += 1024) {
        int k = idx / 10, c = idx - k * 10;
        sm[O_WC + k * 12 + c] = cw2[idx];
    }
    __syncthreads();

    const float* bRow = &sm[O_BC + lane * 516];
    const float* aP   = &sm[O_AC + wg * 1024];

    ull acc0[5], acc1[5];
#pragma unroll
    for (int q = 0; q < 5; q++) { acc0[q] = 0ull; acc1[q] = 0ull; }

    int koff = half * 256;
    for (int k0 = koff; k0 < koff + 256; k0 += 4) {
        float4 bv = *(const float4*)(bRow + k0);
        ulonglong2 aA = *(const ulonglong2*)(aP + 2 * k0);
        ulonglong2 aB = *(const ulonglong2*)(aP + 2 * k0 + 4);
        ull ap[4] = {aA.x, aA.y, aB.x, aB.y};
        float bf[4] = {bv.x, bv.y, bv.z, bv.w};
#pragma unroll
        for (int kk = 0; kk < 4; kk++) {
            ull s = add2(ap[kk], pack2(bf[kk], bf[kk]));
            float2 f = unpack2(s);
            float h0 = fmaxf(f.x, 0.f), h1 = fmaxf(f.y, 0.f);
            ull hh0 = pack2(h0, h0), hh1 = pack2(h1, h1);
            const float* wr = &sm[O_WC + (k0 + kk) * 12];
            ulonglong2 w01 = *(const ulonglong2*)wr;
            ulonglong2 w23 = *(const ulonglong2*)(wr + 4);
            ull w4 = *(const ull*)(wr + 8);
            fma2(acc0[0], hh0, w01.x); fma2(acc0[1], hh0, w01.y);
            fma2(acc0[2], hh0, w23.x); fma2(acc0[3], hh0, w23.y);
            fma2(acc0[4], hh0, w4);
            fma2(acc1[0], hh1, w01.x); fma2(acc1[1], hh1, w01.y);
            fma2(acc1[2], hh1, w23.x); fma2(acc1[3], hh1, w23.y);
            fma2(acc1[4], hh1, w4);
        }
    }

    // strength overlay
    __syncthreads();
#pragma unroll
    for (int it = 0; it < 2; it++) {
        int idx = t + it * 1024;
        int r = idx >> 6, q = (idx & 63) * 4;
        int off = (jbase + r) * 256 + q;
        float4 v = *(const float4*)&sb1[q];
#pragma unroll
        for (int s = 0; s < NSPLIT; s++) {
            float4 u = *(const float4*)&g_sb[s * NN * 256 + off];
            v.x += u.x; v.y += u.y; v.z += u.z; v.w += u.w;
        }
        *(float4*)&sm[O_BC + r * 260 + q] = v;
    }
#pragma unroll
    for (int it = 0; it < 2; it++) {
        int idx = t + it * 1024;
        int r = idx >> 6, q = (idx & 63) * 4;
        int off = (ibase + r) * 256 + q;
        float4 v = {0.f, 0.f, 0.f, 0.f};
#pragma unroll
        for (int s = 0; s < NSPLIT; s++) {
            float4 u = *(const float4*)&g_sa[s * NN * 256 + off];
            v.x += u.x; v.y += u.y; v.z += u.z; v.w += u.w;
        }
        float* dst = &sm[O_AC + (r >> 1) * 512 + q * 2 + (r & 1)];
        dst[0] = v.x; dst[2] = v.y; dst[4] = v.z; dst[6] = v.w;
    }
    if (t < 256) sm[O_WC + t] = sw2[t];
    __syncthreads();

    float s0 = 0.f, s1 = 0.f;
    {
        const float* sbRow = &sm[O_BC + lane * 260];
        const float* saP   = &sm[O_AC + wg * 512];
        int k2 = half * 128;
        for (int k0 = k2; k0 < k2 + 128; k0 += 4) {
            float4 bv = *(const float4*)(sbRow + k0);
            ulonglong2 aA = *(const ulonglong2*)(saP + 2 * k0);
            ulonglong2 aB = *(const ulonglong2*)(saP + 2 * k0 + 4);
            float4 wv = *(const float4*)&sm[O_WC + k0];
            ull ap[4] = {aA.x, aA.y, aB.x, aB.y};
            float bf[4] = {bv.x, bv.y, bv.z, bv.w};
            float wf[4] = {wv.x, wv.y, wv.z, wv.w};
#pragma unroll
            for (int kk = 0; kk < 4; kk++) {
                ull s = add2(ap[kk], pack2(bf[kk], bf[kk]));
                float2 f = unpack2(s);
                s0 = fmaf(fmaxf(f.x, 0.f), wf[kk], s0);
                s1 = fmaf(fmaxf(f.y, 0.f), wf[kk], s1);
            }
        }
    }

    // k-half reduction
    __syncthreads();
    ull* red = (ull*)&sm[O_AC];
    int rbase = (wg * 11) * 32 + lane;
    if (half == 1) {
#pragma unroll
        for (int q = 0; q < 5; q++) {
            red[rbase + q * 32] = acc0[q];
            red[rbase + (5 + q) * 32] = acc1[q];
        }
        red[rbase + 10 * 32] = pack2(s0, s1);
    }
    __syncthreads();

    if (half == 0) {
#pragma unroll
        for (int q = 0; q < 5; q++) {
            acc0[q] = add2(acc0[q], red[rbase + q * 32]);
            acc1[q] = add2(acc1[q], red[rbase + (5 + q) * 32]);
        }
        float2 rs = unpack2(red[rbase + 10 * 32]);
        s0 += rs.x; s1 += rs.y;

        int j = jbase + lane;
        float b2[10];
#pragma unroll
        for (int c = 0; c < 10; c++) b2[c] = __ldg(&cb2[c]);
        float sbv = __ldg(&sb2[0]);
        float sv[2] = {s0, s1};
#pragma unroll
        for (int s = 0; s < 2; s++) {
            int i = ibase + 2 * wg + s;
            if (j <= i) continue;
            float l[10];
#pragma unroll
            for (int q = 0; q < 5; q++) {
                float2 f = unpack2(s ? acc1[q] : acc0[q]);
                l[2 * q] = f.x + b2[2 * q];
                l[2 * q + 1] = f.y + b2[2 * q + 1];
            }
            float m = l[0]; int idx = 0;
#pragma unroll
            for (int c = 1; c < 10; c++) if (l[c] > m) { m = l[c]; idx = c; }
            float sum = 0.f;
#pragma unroll
            for (int c = 0; c < 10; c++) sum += __expf(l[c] - m);
            float lse = m + __logf(sum);
            int p = i * (1023 - i) / 2 + j - i - 1;
            float2* o2 = (float2*)(out + (size_t)p * 10);
#pragma unroll
            for (int q = 0; q < 5; q++)
                o2[q] = make_float2(l[2 * q] - lse, l[2 * q + 1] - lse);
            out[10 * PP + p] = (float)idx;
            float x = sv[s] + sbv;
            out[11 * PP + p] = 1.f / (1.f + __expf(-x));
        }
    }
}

extern "C" void kernel_launch(void* const* d_in, const int* in_sizes, int n_in,
                              void* d_out, int out_size) {
    (void)in_sizes; (void)n_in; (void)out_size;
    const float* features = (const float*)d_in[0];
    const float* cw1 = (const float*)d_in[1];
    const float* cb1 = (const float*)d_in[2];
    const float* cw2 = (const float*)d_in[3];
    const float* cb2 = (const float*)d_in[4];
    const float* sw1 = (const float*)d_in[5];
    const float* sb1 = (const float*)d_in[6];
    const float* sw2 = (const float*)d_in[7];
    const float* sb2 = (const float*)d_in[8];
    float* out = (float*)d_out;

    cudaFuncSetAttribute(pair_kernel, cudaFuncAttributeMaxDynamicSharedMemorySize,
                         SMEMF * sizeof(float));

    proj_gemm<<<dim3(24, 8, NSPLIT), 256>>>(features, cw1, sw1);
    pair_kernel<<<136, 1024, SMEMF * sizeof(float)>>>(
        cb1, cw2, cb2, sb1, sw2, sb2, out);
}